// round 6
// baseline (speedup 1.0000x reference)
#include <cuda_runtime.h>
#include <cuda_bf16.h>
#include <cfloat>
#include <math.h>
#include <stdint.h>

#define NB 4
#define NP 8192
#define NC 64
#define NK 16
#define NS 20               // per-slice approx top-k
#define NSR 80              // 4 slices * NS candidates per query
#define NTOT (NB*NP)        // 32768
#define NTILES 64           // 8192/128
#define NEG_SLOPE 0.2f
#define EPS_LN 1e-5f
#define ROWB 144            // padded smem row bytes (64 bf16 = 128B data + 16B pad)

// ---------------- scratch (device globals; no cudaMalloc allowed) ----------------
__device__ __align__(16) float         g_norms[NTOT];
__device__ __align__(16) __nv_bfloat16 g_xhi[NTOT*NC];
__device__ __align__(16) __nv_bfloat16 g_xlo[NTOT*NC];
__device__ __align__(16) float         g_u[NTOT*NC];     // x @ (W1 - W2) + b
__device__ __align__(16) float         g_v[NTOT*NC];     // x @ W2
__device__ __align__(16) int           g_idxS[(size_t)NTOT*NSR];  // approx candidates
__device__ __align__(16) int           g_idx[NTOT*NK];   // exact top-16
__device__ float g_partial[256*128];
__device__ float g_ss[128];

// ================= helpers =================
__device__ __forceinline__ uint32_t smem_u32(const void* p) {
    uint32_t a;
    asm("{ .reg .u64 t; cvta.to.shared.u64 t, %1; cvt.u32.u64 %0, t; }" : "=r"(a) : "l"(p));
    return a;
}
__device__ __forceinline__ void cp16(uint32_t dst, const void* src) {
    asm volatile("cp.async.ca.shared.global [%0], [%1], 16;" :: "r"(dst), "l"(src) : "memory");
}
#define CP_COMMIT() asm volatile("cp.async.commit_group;" ::: "memory")
#define CP_WAIT(n)  asm volatile("cp.async.wait_group %0;" :: "n"(n) : "memory")

#define LDSM4(rr, addr) \
    asm volatile("ldmatrix.sync.aligned.m8n8.x4.shared.b16 {%0,%1,%2,%3}, [%4];" \
        : "=r"((rr)[0]), "=r"((rr)[1]), "=r"((rr)[2]), "=r"((rr)[3]) : "r"(addr))

#define MMA16816(c0,c1,c2,c3, a, bb) \
    asm volatile("mma.sync.aligned.m16n8k16.row.col.f32.bf16.bf16.f32 " \
        "{%0,%1,%2,%3},{%4,%5,%6,%7},{%8,%9},{%0,%1,%2,%3};" \
        : "+f"(c0), "+f"(c1), "+f"(c2), "+f"(c3) \
        : "r"((a)[0]), "r"((a)[1]), "r"((a)[2]), "r"((a)[3]), "r"((bb)[0]), "r"((bb)[1]))

// SMEM layout (bytes from dynamic smem base)
#define SM_QHI 0
#define SM_QLO 18432
#define SM_C(p) (36864 + (p)*36864)     // hi at +0, lo at +18432
#define SM_TN  110592                    // 2 x 128 floats
#define SM_TOTAL 111616

// ---------------- kernel 1: projections u, v, norms, bf16 hi/lo split ----------------
__global__ void proj_kernel(const float* __restrict__ x,
                            const float* __restrict__ W,
                            const float* __restrict__ bvec) {
    __shared__ float sx[8][NC];
    int warp = threadIdx.x >> 5, lane = threadIdx.x & 31;
    int row = blockIdx.x * 8 + warp;

    float x0 = x[row*NC + lane];
    float x1 = x[row*NC + 32 + lane];
    sx[warp][lane] = x0;
    sx[warp][lane+32] = x1;

    __nv_bfloat16 h0 = __float2bfloat16(x0);
    __nv_bfloat16 h1 = __float2bfloat16(x1);
    g_xhi[row*NC + lane]      = h0;
    g_xhi[row*NC + 32 + lane] = h1;
    g_xlo[row*NC + lane]      = __float2bfloat16(x0 - __bfloat162float(h0));
    g_xlo[row*NC + 32 + lane] = __float2bfloat16(x1 - __bfloat162float(h1));

    float nrm = x0*x0 + x1*x1;
    #pragma unroll
    for (int off = 16; off; off >>= 1) nrm += __shfl_xor_sync(0xFFFFFFFFu, nrm, off);
    if (lane == 0) g_norms[row] = nrm;
    __syncwarp();

    int o0 = lane, o1 = lane + 32;
    float au0 = bvec[o0], au1 = bvec[o1];
    float av0 = 0.f, av1 = 0.f;
    #pragma unroll
    for (int c = 0; c < NC; c++) {
        float xc = sx[warp][c];
        float w1a = W[c*NC + o0];
        float w1b = W[c*NC + o1];
        float w2a = W[(NC + c)*NC + o0];
        float w2b = W[(NC + c)*NC + o1];
        au0 = fmaf(xc, w1a - w2a, au0);
        au1 = fmaf(xc, w1b - w2b, au1);
        av0 = fmaf(xc, w2a, av0);
        av1 = fmaf(xc, w2b, av1);
    }
    g_u[row*NC + o0] = au0;  g_u[row*NC + o1] = au1;
    g_v[row*NC + o0] = av0;  g_v[row*NC + o1] = av1;
}

// ---------------- kernel 2: HMMA approx KNN ----------------
__device__ __forceinline__ void issue_tile(uint32_t sb, int p, int crow) {
    int tid = threadIdx.x;
    #pragma unroll
    for (int i = tid; i < 2048; i += 256) {
        int half = i >> 10, r = (i >> 3) & 127, ch = i & 7;
        const __nv_bfloat16* src = (half ? g_xlo : g_xhi) + (size_t)(crow + r)*NC + ch*8;
        cp16(sb + SM_C(p) + half*18432 + r*ROWB + ch*16, src);
    }
    if (tid < 32) cp16(sb + SM_TN + p*512 + tid*16, g_norms + crow + tid*4);
}

// insert into per-thread top-NS (key packs candidate-local-id in low 11 bits)
__device__ __forceinline__ void ins(float key, float (&bd)[NS], float& cm, int& cp) {
    if (key < cm) {
        #pragma unroll
        for (int k = 0; k < NS; k++) if (k == cp) bd[k] = key;
        float m = bd[0]; int mp = 0;
        #pragma unroll
        for (int k = 1; k < NS; k++) { if (bd[k] > m) { m = bd[k]; mp = k; } }
        cm = m; cp = mp;
    }
}

__global__ void __launch_bounds__(256) knn_kernel() {
    extern __shared__ char smem[];
    uint32_t sb = smem_u32(smem);
    int tid = threadIdx.x, lane = tid & 31, warp = tid >> 5;
    int b  = blockIdx.x >> 6;
    int qt = blockIdx.x & 63;
    int qbase = b*NP + qt*128;
    int cb0   = b*NP;

    // prologue: Q tiles + candidate tiles 0,1
    #pragma unroll
    for (int i = tid; i < 2048; i += 256) {
        int half = i >> 10, r = (i >> 3) & 127, ch = i & 7;
        const __nv_bfloat16* src = (half ? g_xlo : g_xhi) + (size_t)(qbase + r)*NC + ch*8;
        cp16(sb + (half ? SM_QLO : SM_QHI) + r*ROWB + ch*16, src);
    }
    issue_tile(sb, 0, cb0);
    CP_COMMIT();
    issue_tile(sb, 1, cb0 + 128);
    CP_COMMIT();
    CP_WAIT(1);           // Q + tile0 complete
    __syncthreads();

    // A fragments (persistent): rows warp*16 + 0..15, K=64 -> 4 k-blocks, hi & lo
    uint32_t ahi[4][4], alo[4][4];
    {
        int g  = lane >> 3;
        int lr = (lane & 7) + ((g & 1) << 3);
        int c8 = (g >> 1) << 3;
        #pragma unroll
        for (int kb = 0; kb < 4; kb++) {
            uint32_t off = (uint32_t)(warp*16 + lr)*ROWB + (kb*16 + c8)*2;
            LDSM4(ahi[kb], sb + SM_QHI + off);
            LDSM4(alo[kb], sb + SM_QLO + off);
        }
    }

    float k0[NS], k1[NS];
    #pragma unroll
    for (int k = 0; k < NS; k++) { k0[k] = FLT_MAX; k1[k] = FLT_MAX; }
    float cm0 = FLT_MAX, cm1 = FLT_MAX; int cp0 = 0, cp1 = 0;

    // B lane addressing (within each ldmatrix.x4: matrices = (kb,kg0),(kb,kg1),(kb+1,kg0),(kb+1,kg1))
    int bg  = lane >> 3;
    int brow = lane & 7;
    uint32_t bcol = (uint32_t)(((bg >> 1)*16 + (bg & 1)*8) * 2);

    for (int t = 0; t < NTILES; t++) {
        int p = t & 1;
        if (t > 0) {
            if (t < NTILES-1) { CP_WAIT(1); } else { CP_WAIT(0); }
            __syncthreads();
        }
        const float* tn = (const float*)(smem + SM_TN + p*512);
        uint32_t chi = sb + SM_C(p), clo = chi + 18432;

        #pragma unroll 4
        for (int nb = 0; nb < 16; nb++) {
            uint32_t rowoff = (uint32_t)(nb*8 + brow)*ROWB + bcol;
            uint32_t bh[4], bh2[4], bl[4], bl2[4];
            LDSM4(bh,  chi + rowoff);        // kb 0,1
            LDSM4(bh2, chi + rowoff + 64);   // kb 2,3
            LDSM4(bl,  clo + rowoff);
            LDSM4(bl2, clo + rowoff + 64);

            float c0 = 0.f, c1 = 0.f, c2 = 0.f, c3 = 0.f;
            // hi*hi
            MMA16816(c0,c1,c2,c3, ahi[0], (bh  + 0));
            MMA16816(c0,c1,c2,c3, ahi[1], (bh  + 2));
            MMA16816(c0,c1,c2,c3, ahi[2], (bh2 + 0));
            MMA16816(c0,c1,c2,c3, ahi[3], (bh2 + 2));
            // hi*lo
            MMA16816(c0,c1,c2,c3, ahi[0], (bl  + 0));
            MMA16816(c0,c1,c2,c3, ahi[1], (bl  + 2));
            MMA16816(c0,c1,c2,c3, ahi[2], (bl2 + 0));
            MMA16816(c0,c1,c2,c3, ahi[3], (bl2 + 2));
            // lo*hi
            MMA16816(c0,c1,c2,c3, alo[0], (bh  + 0));
            MMA16816(c0,c1,c2,c3, alo[1], (bh  + 2));
            MMA16816(c0,c1,c2,c3, alo[2], (bh2 + 0));
            MMA16816(c0,c1,c2,c3, alo[3], (bh2 + 2));

            int colb = nb*8 + 2*(lane & 3);
            float cn0 = tn[colb], cn1 = tn[colb + 1];
            int lid0 = t*32 + nb*2, lid1 = lid0 + 1;
            float d0 = fmaf(c0, -2.f, cn0);
            float d1 = fmaf(c1, -2.f, cn1);
            float d2 = fmaf(c2, -2.f, cn0);
            float d3 = fmaf(c3, -2.f, cn1);
            ins(__uint_as_float((__float_as_uint(d0) & 0xFFFFF800u) | lid0), k0, cm0, cp0);
            ins(__uint_as_float((__float_as_uint(d1) & 0xFFFFF800u) | lid1), k0, cm0, cp0);
            ins(__uint_as_float((__float_as_uint(d2) & 0xFFFFF800u) | lid0), k1, cm1, cp1);
            ins(__uint_as_float((__float_as_uint(d3) & 0xFFFFF800u) | lid1), k1, cm1, cp1);
        }
        __syncthreads();   // everyone done reading buffer p
        if (t + 2 < NTILES) {
            issue_tile(sb, p, cb0 + (t + 2)*128);
            CP_COMMIT();
        }
    }

    // write candidate slices: 4 threads per row, NS each
    int q0 = qbase + warp*16 + (lane >> 2);
    int q1 = q0 + 8;
    int slot = lane & 3;
    #pragma unroll
    for (int k = 0; k < NS; k++) {
        uint32_t bits = __float_as_uint(k0[k]);
        int lid = bits & 0x7FF;
        int w = lid & 31;
        int col = (lid >> 5)*128 + (w >> 1)*8 + 2*(lane & 3) + (w & 1);
        g_idxS[(size_t)q0*NSR + slot*NS + k] = b*NP + col;
        bits = __float_as_uint(k1[k]);
        lid = bits & 0x7FF;
        w = lid & 31;
        col = (lid >> 5)*128 + (w >> 1)*8 + 2*(lane & 3) + (w & 1);
        g_idxS[(size_t)q1*NSR + slot*NS + k] = b*NP + col;
    }
}

// ---------------- kernel 3: exact fp32 refine (top-16 of 80 candidates) ----------------
__global__ void refine_kernel(const float* __restrict__ x) {
    int i = blockIdx.x * blockDim.x + threadIdx.x;

    int cj[NSR];
    #pragma unroll
    for (int k = 0; k < NSR; k++) cj[k] = g_idxS[(size_t)i*NSR + k];
    // ascending index order (tie semantics: smaller index wins)
    for (int a = 1; a < NSR; a++) {
        int v = cj[a]; int bp = a - 1;
        while (bp >= 0 && cj[bp] > v) { cj[bp+1] = cj[bp]; bp--; }
        cj[bp+1] = v;
    }

    float q[NC];
    #pragma unroll
    for (int c = 0; c < NC; c += 4) {
        float4 t4 = *(const float4*)(x + (size_t)i*NC + c);
        q[c] = t4.x; q[c+1] = t4.y; q[c+2] = t4.z; q[c+3] = t4.w;
    }

    float bestd[NK]; int besti[NK];
    #pragma unroll
    for (int k = 0; k < NK; k++) { bestd[k] = FLT_MAX; besti[k] = 0; }
    float cm = FLT_MAX; int cp = 0;

    for (int k = 0; k < NSR; k++) {
        int j = cj[k];
        const float* cp_ = x + (size_t)j*NC;
        float a0 = 0.f, a1 = 0.f, a2 = 0.f, a3 = 0.f;
        #pragma unroll
        for (int c = 0; c < NC; c += 4) {
            float4 t4 = *(const float4*)(cp_ + c);
            a0 = fmaf(q[c],   t4.x, a0);
            a1 = fmaf(q[c+1], t4.y, a1);
            a2 = fmaf(q[c+2], t4.z, a2);
            a3 = fmaf(q[c+3], t4.w, a3);
        }
        float d = g_norms[j] - 2.f * ((a0 + a1) + (a2 + a3));
        if (d < cm) {
            bestd[cp] = d; besti[cp] = j;
            float m = bestd[0]; int mp = 0;
            #pragma unroll
            for (int kk = 1; kk < NK; kk++) { if (bestd[kk] > m) { m = bestd[kk]; mp = kk; } }
            cm = m; cp = mp;
        }
    }
    #pragma unroll
    for (int k = 0; k < NK; k++) g_idx[(size_t)i*NK + k] = besti[k];
}

// ---------------- kernel 4: per-channel sum / sumsq ----------------
__global__ void stats_kernel() {
    __shared__ float red_s[8][NC];
    __shared__ float red_q[8][NC];
    int warp = threadIdx.x >> 5, lane = threadIdx.x & 31;
    int gw = blockIdx.x * 8 + warp;

    float s10 = 0.f, s11 = 0.f, s20 = 0.f, s21 = 0.f;
    for (int i = gw; i < NTOT; i += 2048) {
        const float* up = g_u + (size_t)i*NC;
        float u0 = up[lane], u1 = up[lane+32];
        const int* ip = g_idx + (size_t)i*NK;
        #pragma unroll
        for (int k = 0; k < NK; k++) {
            int j = ip[k];
            const float* vp = g_v + (size_t)j*NC;
            float h0 = u0 + vp[lane];
            float h1 = u1 + vp[lane+32];
            s10 += h0; s20 = fmaf(h0, h0, s20);
            s11 += h1; s21 = fmaf(h1, h1, s21);
        }
    }
    red_s[warp][lane] = s10;  red_s[warp][lane+32] = s11;
    red_q[warp][lane] = s20;  red_q[warp][lane+32] = s21;
    __syncthreads();
    if (threadIdx.x < NC) {
        float ts = 0.f, tq = 0.f;
        #pragma unroll
        for (int w = 0; w < 8; w++) { ts += red_s[w][threadIdx.x]; tq += red_q[w][threadIdx.x]; }
        g_partial[blockIdx.x*128 + threadIdx.x]      = ts;
        g_partial[blockIdx.x*128 + 64 + threadIdx.x] = tq;
    }
}

// ---------------- kernel 5: final reduction -> scale/shift ----------------
__global__ void reduce_kernel(const float* __restrict__ gamma,
                              const float* __restrict__ beta) {
    __shared__ float acc[8][128];
    int tid = threadIdx.x;        // 1024
    int chan = tid & 127, grp = tid >> 7;
    float s = 0.f;
    for (int blk = grp; blk < 256; blk += 8) s += g_partial[blk*128 + chan];
    acc[grp][chan] = s;
    __syncthreads();
    if (tid < 128) {
        float tot = 0.f;
        #pragma unroll
        for (int w = 0; w < 8; w++) tot += acc[w][tid];
        acc[0][tid] = tot;
    }
    __syncthreads();
    if (tid < NC) {
        double N    = (double)NTOT * (double)NK;
        double mean = (double)acc[0][tid] / N;
        double msq  = (double)acc[0][64 + tid] / N;
        double var  = msq - mean*mean;
        double inv  = 1.0 / sqrt(var + (double)EPS_LN);
        double sc   = (double)gamma[tid] * inv;
        g_ss[tid]      = (float)sc;
        g_ss[64 + tid] = (float)((double)beta[tid] - mean*sc);
    }
}

// ---------------- kernel 6: normalize + leaky-relu + max over K ----------------
__global__ void out_kernel(float* __restrict__ out) {
    int warp = threadIdx.x >> 5, lane = threadIdx.x & 31;
    int gw = blockIdx.x * 8 + warp;
    float sc0 = g_ss[lane],      sc1 = g_ss[lane+32];
    float sh0 = g_ss[64 + lane], sh1 = g_ss[96 + lane];

    for (int i = gw; i < NTOT; i += 2048) {
        const float* up = g_u + (size_t)i*NC;
        float u0 = up[lane], u1 = up[lane+32];
        const int* ip = g_idx + (size_t)i*NK;
        float m0 = -FLT_MAX, m1 = -FLT_MAX;
        #pragma unroll
        for (int k = 0; k < NK; k++) {
            int j = ip[k];
            const float* vp = g_v + (size_t)j*NC;
            float h0 = u0 + vp[lane];
            float h1 = u1 + vp[lane+32];
            float n0 = fmaf(h0, sc0, sh0);
            float n1 = fmaf(h1, sc1, sh1);
            float a0 = (n0 >= 0.f) ? n0 : NEG_SLOPE*n0;
            float a1 = (n1 >= 0.f) ? n1 : NEG_SLOPE*n1;
            m0 = fmaxf(m0, a0);
            m1 = fmaxf(m1, a1);
        }
        out[(size_t)i*NC + lane]      = m0;
        out[(size_t)i*NC + lane+32]   = m1;
    }
}

// ---------------- launch ----------------
extern "C" void kernel_launch(void* const* d_in, const int* in_sizes, int n_in,
                              void* d_out, int out_size) {
    const float* x     = (const float*)d_in[0];
    const float* W     = (const float*)d_in[2];
    const float* bvec  = (const float*)d_in[3];
    const float* gamma = (const float*)d_in[4];
    const float* beta  = (const float*)d_in[5];
    float* out = (float*)d_out;

    cudaFuncSetAttribute(knn_kernel, cudaFuncAttributeMaxDynamicSharedMemorySize, SM_TOTAL);

    proj_kernel<<<NTOT/8, 256>>>(x, W, bvec);
    knn_kernel<<<NB*64, 256, SM_TOTAL>>>();
    refine_kernel<<<NTOT/256, 256>>>(x);
    stats_kernel<<<256, 256>>>();
    reduce_kernel<<<1, 1024>>>(gamma, beta);
    out_kernel<<<256, 256>>>(out);
}